// round 4
// baseline (speedup 1.0000x reference)
#include <cuda_runtime.h>
#include <math.h>

// Problem constants
#define C_CH   16
#define T_LEN  8192
#define F_LEN  16384
#define HF     8192          // F/2, the live half of the spectrum
#define K_MODES 8
#define N_ITERS 19           // MAX_N - 1
#define ALPHA_F 2000.0f
#define NBLK   128
#define NTHR   1024

// Output layout modes
#define MODE_R 0   // all-float32: [u_out | Re(u_hat2) | Re(omega)]           (2,097,312 f32)
#define MODE_C 1   // complex64 concat: [u_out(c64) | u_hat2 | omega]
#define MODE_M 2   // mixed: [u_out(f32) | u_hat2(c64 interleaved) | omega]

// ---------------- device state (no allocations allowed) ----------------
__device__ float2   g_fpos[HF * C_CH];            // fft bins 0..8191, layout [j][c_shifted]
__device__ float2   g_upos[HF * K_MODES * C_CH];  // final u, layout [j][k][c_shifted]
__device__ float    g_part[2][NBLK][16];          // per-block partials
__device__ float    g_omega[(N_ITERS + 1) * K_MODES];
__device__ unsigned g_cnt;
__device__ unsigned g_gen;

// ---------------- software grid barrier (128 co-resident blocks) -------
__device__ __forceinline__ void grid_barrier(unsigned target) {
    __syncthreads();
    if (threadIdx.x == 0) {
        __threadfence();
        unsigned old = atomicAdd(&g_cnt, 1u);
        if (old == gridDim.x - 1u) {
            g_cnt = 0u;
            __threadfence();
            atomicExch(&g_gen, target);
        } else {
            while (atomicAdd(&g_gen, 0u) < target) { __nanosleep(64); }
        }
    }
    __syncthreads();
}

// ---------------- in-place radix-2 DIT FFT on shared memory ------------
// Input must be loaded bit-reversed; output is natural order.
__device__ __forceinline__ void fft_smem(float2* s, int logN, float sign) {
    const int N   = 1 << logN;
    const int tid = threadIdx.x;
    const int nt  = blockDim.x;
    for (int st = 1; st <= logN; ++st) {
        const int   half = 1 << (st - 1);
        const float base = sign * 3.14159265358979323846f / (float)half;
        for (int b = tid; b < (N >> 1); b += nt) {
            int jj = b & (half - 1);
            int i1 = ((b >> (st - 1)) << st) + jj;
            int i2 = i1 + half;
            float sn, cs;
            sincosf(base * (float)jj, &sn, &cs);
            float2 a  = s[i1];
            float2 bb = s[i2];
            float tx = bb.x * cs - bb.y * sn;
            float ty = bb.x * sn + bb.y * cs;
            s[i1] = make_float2(a.x + tx, a.y + ty);
            s[i2] = make_float2(a.x - tx, a.y - ty);
        }
        __syncthreads();
    }
}

// ---------------- kernels ----------------------------------------------
__global__ void init_kernel() {
    if (threadIdx.x == 0) { g_cnt = 0u; g_gen = 0u; }
    if (threadIdx.x < K_MODES)
        g_omega[threadIdx.x] = 0.0625f * (float)threadIdx.x;  // 0.5/K * k
}

// Mirror-extend signal (per channel), FFT-16384, keep bins 0..8191.
// NOTE: reference applies fftshift with axes=None, which ALSO rolls the
// channel axis by C/2=8. We bake that in here: raw channel c is stored as
// "shifted" channel (c+8)&15; all downstream channel indices are shifted.
__global__ __launch_bounds__(NTHR, 1) void fwd_fft_kernel(const float* __restrict__ sig) {
    extern __shared__ float2 sh[];
    const int c = blockIdx.x;
    const float* sc = sig + c * T_LEN;
    for (int i = threadIdx.x; i < F_LEN; i += blockDim.x) {
        float v;
        if (i < 4096)       v = sc[4095 - i];
        else if (i < 12288) v = sc[i - 4096];
        else                v = sc[20479 - i];
        sh[__brev((unsigned)i) >> 18] = make_float2(v, 0.f);
    }
    __syncthreads();
    fft_smem(sh, 14, -1.f);
    const int cshift = (c + 8) & 15;
    for (int j = threadIdx.x; j < HF; j += blockDim.x)
        g_fpos[j * C_CH + cshift] = sh[j];
}

// Persistent scan: u[8] lives in registers; 1 grid barrier per iteration.
__global__ __launch_bounds__(NTHR, 1) void iterate_kernel() {
    const int tid  = threadIdx.x;
    const int e    = blockIdx.x * NTHR + tid;          // element id = j*16 + c
    const int j    = e >> 4;
    const int lane = tid & 31;
    const int wid  = tid >> 5;
    const float fh = (float)j * (1.0f / (float)F_LEN);

    __shared__ float s_omega[K_MODES];
    __shared__ float s_wpart[32][16];
    __shared__ float s_red[16];

    if (tid < K_MODES) s_omega[tid] = 0.0625f * (float)tid;
    __syncthreads();

    const float2 fp = g_fpos[e];
    float2 u[K_MODES];
#pragma unroll
    for (int k = 0; k < K_MODES; ++k) u[k] = make_float2(0.f, 0.f);
    float2 sum = make_float2(0.f, 0.f);

    for (int it = 0; it < N_ITERS; ++it) {
        sum.x += u[K_MODES - 1].x - u[0].x;
        sum.y += u[K_MODES - 1].y - u[0].y;
        float2 prev_new = make_float2(0.f, 0.f);
#pragma unroll
        for (int k = 0; k < K_MODES; ++k) {
            if (k > 0) {
                sum.x += prev_new.x - u[k].x;
                sum.y += prev_new.y - u[k].y;
            }
            float d      = fh - s_omega[k];
            float invden = 1.0f / (1.0f + ALPHA_F * d * d);
            float2 un    = make_float2((fp.x - sum.x) * invden, (fp.y - sum.y) * invden);
            u[k] = un;
            prev_new = un;
            float mag = un.x * un.x + un.y * un.y;
            float num = fh * mag;
#pragma unroll
            for (int o = 16; o; o >>= 1) {
                mag += __shfl_down_sync(0xffffffffu, mag, o);
                num += __shfl_down_sync(0xffffffffu, num, o);
            }
            if (lane == 0) {
                s_wpart[wid][k * 2 + 0] = num;
                s_wpart[wid][k * 2 + 1] = mag;
            }
        }
        __syncthreads();
        const int buf = it & 1;
        if (tid < 16) {
            float acc = 0.f;
#pragma unroll
            for (int w = 0; w < 32; ++w) acc += s_wpart[w][tid];
            g_part[buf][blockIdx.x][tid] = acc;
        }
        grid_barrier((unsigned)(it + 1));
        if (tid < 16) {
            const volatile float* vp = &g_part[buf][0][tid];
            float acc = 0.f;
            for (int b = 0; b < NBLK; ++b) acc += vp[b * 16];
            s_red[tid] = acc;
        }
        __syncthreads();
        if (tid < K_MODES) {
            float om = s_red[2 * tid] / s_red[2 * tid + 1];
            s_omega[tid] = om;
            if (blockIdx.x == 0) g_omega[(it + 1) * K_MODES + tid] = om;
        }
        __syncthreads();
    }

    const int c = e & 15;
#pragma unroll
    for (int k = 0; k < K_MODES; ++k)
        g_upos[(j * K_MODES + k) * C_CH + c] = u[k];
}

// Per (k,c_shifted) column: symmetric spectrum -> ifft-16384 -> slice ->
// u_out (channel-unshifted), then fft-8192 + fftshift + conj -> u_hat2
// (keeps shifted channel order, matching the reference).
__global__ __launch_bounds__(NTHR, 1) void recon_kernel(float* __restrict__ dout, int mode,
                                                        long long limf /* float units */) {
    extern __shared__ float2 sh[];
    const int b   = blockIdx.x;
    const int k   = b >> 4;
    const int c   = b & 15;           // shifted channel index
    const int tid = threadIdx.x;
    const long long lim2 = limf >> 1; // float2 units

    // v = ifftshift(u_hat) with the reference's exact overwrite semantics
    for (int i = tid; i < F_LEN; i += NTHR) {
        float2 p;
        if (i == 0) {
            float2 q = g_upos[(0 * K_MODES + k) * C_CH + c];
            p = make_float2(q.x, -q.y);
        } else if (i < HF) {
            p = g_upos[(i * K_MODES + k) * C_CH + c];
        } else if (i == HF) {
            float2 q = g_upos[((HF - 1) * K_MODES + k) * C_CH + c];
            p = make_float2(q.x, -q.y);
        } else {
            float2 q = g_upos[((F_LEN - i) * K_MODES + k) * C_CH + c];
            p = make_float2(q.x, -q.y);
        }
        sh[__brev((unsigned)i) >> 18] = p;
    }
    __syncthreads();
    fft_smem(sh, 14, +1.f);

    // u_c time series: real part of bins [4096, 12288), scaled by 1/F
    float w[8];
    const float inv = 1.0f / (float)F_LEN;
#pragma unroll
    for (int q = 0; q < 8; ++q) {
        int t = tid + q * NTHR;
        w[q] = sh[4096 + t].x * inv;
    }
    __syncthreads();

    // ---- u_out[k][t][(c+8)&15]: final channel ifftshift -> raw order ----
    const int cs = (c + 8) & 15;
    if (mode == MODE_C) {
        float2* o = (float2*)dout;
#pragma unroll
        for (int q = 0; q < 8; ++q) {
            int t = tid + q * NTHR;
            long long idx = (long long)(k * T_LEN + t) * C_CH + cs;
            if (idx < lim2) o[idx] = make_float2(w[q], 0.f);
        }
    } else {  // MODE_R and MODE_M: plain float32
#pragma unroll
        for (int q = 0; q < 8; ++q) {
            int t = tid + q * NTHR;
            long long idx = (long long)(k * T_LEN + t) * C_CH + cs;
            if (idx < limf) dout[idx] = w[q];
        }
    }

    // forward FFT of the slice (length 8192)
#pragma unroll
    for (int q = 0; q < 8; ++q) {
        int t = tid + q * NTHR;
        sh[__brev((unsigned)t) >> 19] = make_float2(w[q], 0.f);
    }
    __syncthreads();
    fft_smem(sh, 13, -1.f);

    // ---- u_hat2[t][k][c] = conj(X[(t+4096) & 8191]) (shifted channel) ----
    if (mode == MODE_R) {
        const long long base = (long long)T_LEN * K_MODES * C_CH;  // floats
        for (int t = tid; t < T_LEN; t += NTHR) {
            float2 X = sh[(t + 4096) & 8191];
            long long idx = base + ((long long)t * K_MODES + k) * C_CH + c;
            if (idx < limf) dout[idx] = X.x;  // real part of conj == real part
        }
    } else {
        const long long base2 = (mode == MODE_M)
            ? (long long)(T_LEN * K_MODES * C_CH / 2)
            : (long long)(T_LEN * K_MODES * C_CH);
        float2* o = (float2*)dout;
        for (int t = tid; t < T_LEN; t += NTHR) {
            float2 X = sh[(t + 4096) & 8191];
            long long idx = base2 + ((long long)t * K_MODES + k) * C_CH + c;
            if (idx < lim2) o[idx] = make_float2(X.x, -X.y);
        }
    }
}

__global__ void omega_out_kernel(float* __restrict__ dout, int mode, long long limf) {
    int i = threadIdx.x;
    if (i >= (N_ITERS + 1) * K_MODES) return;
    if (mode == MODE_R) {
        long long idx = 2097152LL + i;
        if (idx < limf) dout[idx] = g_omega[i];
    } else {
        long long base2 = (mode == MODE_M) ? 1572864LL : 2097152LL;
        long long idx = base2 + i;
        if (idx < (limf >> 1)) ((float2*)dout)[idx] = make_float2(g_omega[i], 0.f);
    }
}

// ---------------- launch ------------------------------------------------
extern "C" void kernel_launch(void* const* d_in, const int* in_sizes, int n_in,
                              void* d_out, int out_size) {
    const float* sig = (const float*)d_in[0];

    int mode;
    if (out_size == 4194624)      mode = MODE_C;
    else if (out_size == 3146048) mode = MODE_M;
    else                          mode = MODE_R;   // confirmed: 2,097,312 float32
    const long long limf = (long long)out_size;

    cudaFuncSetAttribute(fwd_fft_kernel, cudaFuncAttributeMaxDynamicSharedMemorySize, 131072);
    cudaFuncSetAttribute(recon_kernel,   cudaFuncAttributeMaxDynamicSharedMemorySize, 131072);

    init_kernel<<<1, 32>>>();
    fwd_fft_kernel<<<C_CH, NTHR, 131072>>>(sig);
    iterate_kernel<<<NBLK, NTHR>>>();
    recon_kernel<<<NBLK, NTHR, 131072>>>((float*)d_out, mode, limf);
    omega_out_kernel<<<1, 192>>>((float*)d_out, mode, limf);
}

// round 5
// speedup vs baseline: 1.0576x; 1.0576x over previous
#include <cuda_runtime.h>
#include <math.h>

// Problem constants
#define C_CH   16
#define T_LEN  8192
#define F_LEN  16384
#define HF     8192
#define K_MODES 8
#define N_ITERS 19
#define ALPHA_F 2000.0f
#define NBLK   128
#define NTHR   1024

// Output layout modes
#define MODE_R 0   // all-float32: [u_out | Re(u_hat2) | Re(omega)]  (2,097,312 f32) -- confirmed
#define MODE_C 1
#define MODE_M 2

// ---------------- device state ----------------
__device__ float2   g_fpos[HF * C_CH];            // [j][c_shifted]
__device__ float2   g_upos[HF * K_MODES * C_CH];  // [j][k][c_shifted]
__device__ float    g_part[2][NBLK][16];
__device__ float    g_omega[(N_ITERS + 1) * K_MODES];
__device__ unsigned g_cnt;
__device__ unsigned g_gen;

// ---------------- software grid barrier ----------------
__device__ __forceinline__ void grid_barrier(unsigned target) {
    __syncthreads();
    if (threadIdx.x == 0) {
        __threadfence();
        unsigned old = atomicAdd(&g_cnt, 1u);
        if (old == gridDim.x - 1u) {
            g_cnt = 0u;
            __threadfence();
            atomicExch(&g_gen, target);
        } else {
            while (atomicAdd(&g_gen, 0u) < target) { }
        }
    }
    __syncthreads();
}

// ---------------- fused radix-2^2 DIT FFT on shared memory ----------------
// Identical computation graph to 14 radix-2 stages with bit-reversed input,
// but processes two stages per pass: half the smem traffic, 1/4 the sincos.
// Twiddles via sincospif with exact power-of-two fraction arguments.
__device__ __forceinline__ void fft_smem(float2* s, int logN, float sign) {
    const int N   = 1 << logN;
    const int tid = threadIdx.x;
    const int nt  = blockDim.x;
    int st = 1;
    for (; st + 1 <= logN; st += 2) {
        const int   h     = 1 << (st - 1);
        const float inv2h = 1.0f / (float)(2 * h);
        for (int g = tid; g < (N >> 2); g += nt) {
            const int jj   = g & (h - 1);
            const int base = ((g >> (st - 1)) << (st + 1)) + jj;
            float2 a0 = s[base];
            float2 a1 = s[base + h];
            float2 a2 = s[base + 2 * h];
            float2 a3 = s[base + 3 * h];
            float sp, cp;
            sincospif((float)jj * inv2h, &sp, &cp);   // w2 = exp(sign*i*pi*jj/(2h))
            const float s2 = sign * sp, c2 = cp;
            const float c1 = c2 * c2 - s2 * s2;       // w1 = w2^2
            const float s1 = 2.0f * c2 * s2;
            // stage st: (a0,a1) and (a2,a3), twiddle w1
            float t1x = a1.x * c1 - a1.y * s1, t1y = a1.x * s1 + a1.y * c1;
            float b0x = a0.x + t1x, b0y = a0.y + t1y;
            float b1x = a0.x - t1x, b1y = a0.y - t1y;
            float t3x = a3.x * c1 - a3.y * s1, t3y = a3.x * s1 + a3.y * c1;
            float b2x = a2.x + t3x, b2y = a2.y + t3y;
            float b3x = a2.x - t3x, b3y = a2.y - t3y;
            // stage st+1: (b0,b2) twiddle w2 ; (b1,b3) twiddle sign*i*w2
            float ux = b2x * c2 - b2y * s2, uy = b2x * s2 + b2y * c2;
            float v0x = b3x * c2 - b3y * s2, v0y = b3x * s2 + b3y * c2;
            float vx = -sign * v0y, vy = sign * v0x;
            s[base]         = make_float2(b0x + ux, b0y + uy);
            s[base + h]     = make_float2(b1x + vx, b1y + vy);
            s[base + 2 * h] = make_float2(b0x - ux, b0y - uy);
            s[base + 3 * h] = make_float2(b1x - vx, b1y - vy);
        }
        __syncthreads();
    }
    if (st <= logN) {  // one leftover radix-2 stage (odd logN)
        const int   half = 1 << (st - 1);
        const float invh = 1.0f / (float)half;
        for (int b = tid; b < (N >> 1); b += nt) {
            const int jj = b & (half - 1);
            const int i1 = ((b >> (st - 1)) << st) + jj;
            const int i2 = i1 + half;
            float sp, cp;
            sincospif((float)jj * invh, &sp, &cp);
            const float sn = sign * sp, cs = cp;
            float2 a  = s[i1];
            float2 bb = s[i2];
            float tx = bb.x * cs - bb.y * sn;
            float ty = bb.x * sn + bb.y * cs;
            s[i1] = make_float2(a.x + tx, a.y + ty);
            s[i2] = make_float2(a.x - tx, a.y - ty);
        }
        __syncthreads();
    }
}

// ---------------- kernels ----------------
__global__ void init_kernel() {
    if (threadIdx.x == 0) { g_cnt = 0u; g_gen = 0u; }
    if (threadIdx.x < K_MODES)
        g_omega[threadIdx.x] = 0.0625f * (float)threadIdx.x;
}

// Mirror-extend (per channel), FFT-16384, keep bins 0..8191; channel stored
// shifted by 8 (reference's fftshift over all axes).
__global__ __launch_bounds__(NTHR, 1) void fwd_fft_kernel(const float* __restrict__ sig) {
    extern __shared__ float2 sh[];
    const int c = blockIdx.x;
    const float* sc = sig + c * T_LEN;
    for (int i = threadIdx.x; i < F_LEN; i += blockDim.x) {
        float v;
        if (i < 4096)       v = sc[4095 - i];
        else if (i < 12288) v = sc[i - 4096];
        else                v = sc[20479 - i];
        sh[__brev((unsigned)i) >> 18] = make_float2(v, 0.f);
    }
    __syncthreads();
    fft_smem(sh, 14, -1.f);
    const int cshift = (c + 8) & 15;
    for (int j = threadIdx.x; j < HF; j += blockDim.x)
        g_fpos[j * C_CH + cshift] = sh[j];
}

// Persistent scan: u[8] in registers, 1 grid barrier per iteration.
__global__ __launch_bounds__(NTHR, 1) void iterate_kernel() {
    const int tid  = threadIdx.x;
    const int e    = blockIdx.x * NTHR + tid;   // e = j*16 + c
    const int j    = e >> 4;
    const int lane = tid & 31;
    const int wid  = tid >> 5;
    const float fh = (float)j * (1.0f / (float)F_LEN);

    __shared__ float s_omega[K_MODES];
    __shared__ float s_wpart[32][16];
    __shared__ float s_red[16];

    if (tid < K_MODES) s_omega[tid] = 0.0625f * (float)tid;
    __syncthreads();

    const float2 fp = g_fpos[e];
    float2 u[K_MODES];
#pragma unroll
    for (int k = 0; k < K_MODES; ++k) u[k] = make_float2(0.f, 0.f);
    float2 sum = make_float2(0.f, 0.f);

    for (int it = 0; it < N_ITERS; ++it) {
        sum.x += u[K_MODES - 1].x - u[0].x;
        sum.y += u[K_MODES - 1].y - u[0].y;
        float2 prev_new = make_float2(0.f, 0.f);
#pragma unroll
        for (int k = 0; k < K_MODES; ++k) {
            if (k > 0) {
                sum.x += prev_new.x - u[k].x;
                sum.y += prev_new.y - u[k].y;
            }
            float d      = fh - s_omega[k];
            float invden = 1.0f / (1.0f + ALPHA_F * d * d);
            float2 un    = make_float2((fp.x - sum.x) * invden, (fp.y - sum.y) * invden);
            u[k] = un;
            prev_new = un;
            float mag = un.x * un.x + un.y * un.y;
            float num = fh * mag;
#pragma unroll
            for (int o = 16; o; o >>= 1) {
                mag += __shfl_down_sync(0xffffffffu, mag, o);
                num += __shfl_down_sync(0xffffffffu, num, o);
            }
            if (lane == 0) {
                s_wpart[wid][k * 2 + 0] = num;
                s_wpart[wid][k * 2 + 1] = mag;
            }
        }
        __syncthreads();
        const int buf = it & 1;
        if (tid < 16) {
            float acc = 0.f;
#pragma unroll
            for (int w = 0; w < 32; ++w) acc += s_wpart[w][tid];
            g_part[buf][blockIdx.x][tid] = acc;
        }
        grid_barrier((unsigned)(it + 1));
        // warp-per-value deterministic reduction over 128 block rows (L1-bypassed)
        if (tid < 512) {
            const int v = tid >> 5;          // value index 0..15
            const float* gp = &g_part[buf][0][0];
            float acc = __ldcg(gp + (lane      ) * 16 + v)
                      + __ldcg(gp + (lane +  32) * 16 + v)
                      + __ldcg(gp + (lane +  64) * 16 + v)
                      + __ldcg(gp + (lane +  96) * 16 + v);
#pragma unroll
            for (int o = 16; o; o >>= 1) acc += __shfl_down_sync(0xffffffffu, acc, o);
            if (lane == 0) s_red[v] = acc;
        }
        __syncthreads();
        if (tid < K_MODES) {
            float om = s_red[2 * tid] / s_red[2 * tid + 1];
            s_omega[tid] = om;
            if (blockIdx.x == 0) g_omega[(it + 1) * K_MODES + tid] = om;
        }
        __syncthreads();
    }

    const int c = e & 15;
#pragma unroll
    for (int k = 0; k < K_MODES; ++k)
        g_upos[(j * K_MODES + k) * C_CH + c] = u[k];
}

// Per (k,c_shifted) column: symmetric spectrum -> ifft-16384 -> slice ->
// u_out (unshift channel), then fft-8192 + fftshift + conj -> u_hat2.
__global__ __launch_bounds__(NTHR, 1) void recon_kernel(float* __restrict__ dout, int mode,
                                                        long long limf) {
    extern __shared__ float2 sh[];
    const int b   = blockIdx.x;
    const int k   = b >> 4;
    const int c   = b & 15;
    const int tid = threadIdx.x;
    const long long lim2 = limf >> 1;

    for (int i = tid; i < F_LEN; i += NTHR) {
        float2 p;
        if (i == 0) {
            float2 q = g_upos[(0 * K_MODES + k) * C_CH + c];
            p = make_float2(q.x, -q.y);
        } else if (i < HF) {
            p = g_upos[(i * K_MODES + k) * C_CH + c];
        } else if (i == HF) {
            float2 q = g_upos[((HF - 1) * K_MODES + k) * C_CH + c];
            p = make_float2(q.x, -q.y);
        } else {
            float2 q = g_upos[((F_LEN - i) * K_MODES + k) * C_CH + c];
            p = make_float2(q.x, -q.y);
        }
        sh[__brev((unsigned)i) >> 18] = p;
    }
    __syncthreads();
    fft_smem(sh, 14, +1.f);

    float w[8];
    const float inv = 1.0f / (float)F_LEN;
#pragma unroll
    for (int q = 0; q < 8; ++q) {
        int t = tid + q * NTHR;
        w[q] = sh[4096 + t].x * inv;
    }
    __syncthreads();

    const int cs = (c + 8) & 15;
    if (mode == MODE_C) {
        float2* o = (float2*)dout;
#pragma unroll
        for (int q = 0; q < 8; ++q) {
            int t = tid + q * NTHR;
            long long idx = (long long)(k * T_LEN + t) * C_CH + cs;
            if (idx < lim2) o[idx] = make_float2(w[q], 0.f);
        }
    } else {
#pragma unroll
        for (int q = 0; q < 8; ++q) {
            int t = tid + q * NTHR;
            long long idx = (long long)(k * T_LEN + t) * C_CH + cs;
            if (idx < limf) dout[idx] = w[q];
        }
    }

#pragma unroll
    for (int q = 0; q < 8; ++q) {
        int t = tid + q * NTHR;
        sh[__brev((unsigned)t) >> 19] = make_float2(w[q], 0.f);
    }
    __syncthreads();
    fft_smem(sh, 13, -1.f);

    if (mode == MODE_R) {
        const long long base = (long long)T_LEN * K_MODES * C_CH;
        for (int t = tid; t < T_LEN; t += NTHR) {
            float2 X = sh[(t + 4096) & 8191];
            long long idx = base + ((long long)t * K_MODES + k) * C_CH + c;
            if (idx < limf) dout[idx] = X.x;
        }
    } else {
        const long long base2 = (mode == MODE_M)
            ? (long long)(T_LEN * K_MODES * C_CH / 2)
            : (long long)(T_LEN * K_MODES * C_CH);
        float2* o = (float2*)dout;
        for (int t = tid; t < T_LEN; t += NTHR) {
            float2 X = sh[(t + 4096) & 8191];
            long long idx = base2 + ((long long)t * K_MODES + k) * C_CH + c;
            if (idx < lim2) o[idx] = make_float2(X.x, -X.y);
        }
    }
}

__global__ void omega_out_kernel(float* __restrict__ dout, int mode, long long limf) {
    int i = threadIdx.x;
    if (i >= (N_ITERS + 1) * K_MODES) return;
    if (mode == MODE_R) {
        long long idx = 2097152LL + i;
        if (idx < limf) dout[idx] = g_omega[i];
    } else {
        long long base2 = (mode == MODE_M) ? 1572864LL : 2097152LL;
        long long idx = base2 + i;
        if (idx < (limf >> 1)) ((float2*)dout)[idx] = make_float2(g_omega[i], 0.f);
    }
}

// ---------------- launch ----------------
extern "C" void kernel_launch(void* const* d_in, const int* in_sizes, int n_in,
                              void* d_out, int out_size) {
    const float* sig = (const float*)d_in[0];

    int mode;
    if (out_size == 4194624)      mode = MODE_C;
    else if (out_size == 3146048) mode = MODE_M;
    else                          mode = MODE_R;
    const long long limf = (long long)out_size;

    cudaFuncSetAttribute(fwd_fft_kernel, cudaFuncAttributeMaxDynamicSharedMemorySize, 131072);
    cudaFuncSetAttribute(recon_kernel,   cudaFuncAttributeMaxDynamicSharedMemorySize, 131072);

    init_kernel<<<1, 32>>>();
    fwd_fft_kernel<<<C_CH, NTHR, 131072>>>(sig);
    iterate_kernel<<<NBLK, NTHR>>>();
    recon_kernel<<<NBLK, NTHR, 131072>>>((float*)d_out, mode, limf);
    omega_out_kernel<<<1, 192>>>((float*)d_out, mode, limf);
}

// round 6
// speedup vs baseline: 1.2297x; 1.1627x over previous
#include <cuda_runtime.h>
#include <math.h>

#define C_CH   16
#define T_LEN  8192
#define F_LEN  16384
#define HF     8192
#define K_MODES 8
#define N_ITERS 19
#define ALPHA_F 2000.0f
#define NBLK   128
#define NTHR   1024

#define MODE_R 0   // all-float32: [u_out | Re(u_hat2) | Re(omega)] (2,097,312 f32) -- confirmed
#define MODE_C 1
#define MODE_M 2

// ---------------- device state ----------------
__device__ float2   g_fpos[HF * C_CH];            // [j][c_shifted]
__device__ float2   g_upos[HF * K_MODES * C_CH];  // [j][k][c_shifted]
__device__ float    g_part[2][NBLK][16];
__device__ float    g_omega[(N_ITERS + 1) * K_MODES];
__device__ unsigned g_cnt;
__device__ unsigned g_gen;

// ---------------- software grid barrier (acquire/release, no atomic spin) ----
__device__ __forceinline__ void grid_barrier(unsigned target) {
    __syncthreads();
    if (threadIdx.x == 0) {
        __threadfence();
        unsigned old = atomicAdd(&g_cnt, 1u);
        if (old == NBLK - 1u) {
            g_cnt = 0u;
            asm volatile("st.global.release.gpu.b32 [%0], %1;" :: "l"(&g_gen), "r"(target) : "memory");
        } else {
            unsigned v;
            do {
                asm volatile("ld.global.acquire.gpu.b32 %0, [%1];" : "=r"(v) : "l"(&g_gen) : "memory");
            } while (v < target);
        }
    }
    __syncthreads();
}

// ---------------- fused radix-2^2 DIT FFT on shared memory ----------------
// Bit-reversed input, natural output. Two stages per pass.
__device__ __forceinline__ void fft_smem(float2* s, int logN, float sign) {
    const int N   = 1 << logN;
    const int tid = threadIdx.x;
    const int nt  = blockDim.x;
    int st = 1;
    for (; st + 1 <= logN; st += 2) {
        const int   h     = 1 << (st - 1);
        const float inv2h = 1.0f / (float)(2 * h);
        for (int g = tid; g < (N >> 2); g += nt) {
            const int jj   = g & (h - 1);
            const int base = ((g >> (st - 1)) << (st + 1)) + jj;
            float2 a0 = s[base];
            float2 a1 = s[base + h];
            float2 a2 = s[base + 2 * h];
            float2 a3 = s[base + 3 * h];
            float sp, cp;
            sincospif((float)jj * inv2h, &sp, &cp);
            const float s2 = sign * sp, c2 = cp;
            const float c1 = c2 * c2 - s2 * s2;
            const float s1 = 2.0f * c2 * s2;
            float t1x = a1.x * c1 - a1.y * s1, t1y = a1.x * s1 + a1.y * c1;
            float b0x = a0.x + t1x, b0y = a0.y + t1y;
            float b1x = a0.x - t1x, b1y = a0.y - t1y;
            float t3x = a3.x * c1 - a3.y * s1, t3y = a3.x * s1 + a3.y * c1;
            float b2x = a2.x + t3x, b2y = a2.y + t3y;
            float b3x = a2.x - t3x, b3y = a2.y - t3y;
            float ux = b2x * c2 - b2y * s2, uy = b2x * s2 + b2y * c2;
            float v0x = b3x * c2 - b3y * s2, v0y = b3x * s2 + b3y * c2;
            float vx = -sign * v0y, vy = sign * v0x;
            s[base]         = make_float2(b0x + ux, b0y + uy);
            s[base + h]     = make_float2(b1x + vx, b1y + vy);
            s[base + 2 * h] = make_float2(b0x - ux, b0y - uy);
            s[base + 3 * h] = make_float2(b1x - vx, b1y - vy);
        }
        __syncthreads();
    }
    if (st <= logN) {
        const int   half = 1 << (st - 1);
        const float invh = 1.0f / (float)half;
        for (int b = tid; b < (N >> 1); b += nt) {
            const int jj = b & (half - 1);
            const int i1 = ((b >> (st - 1)) << st) + jj;
            const int i2 = i1 + half;
            float sp, cp;
            sincospif((float)jj * invh, &sp, &cp);
            const float sn = sign * sp, cs = cp;
            float2 a  = s[i1];
            float2 bb = s[i2];
            float tx = bb.x * cs - bb.y * sn;
            float ty = bb.x * sn + bb.y * cs;
            s[i1] = make_float2(a.x + tx, a.y + ty);
            s[i2] = make_float2(a.x - tx, a.y - ty);
        }
        __syncthreads();
    }
}

// ---------------- kernels ----------------
__global__ void init_kernel() {
    if (threadIdx.x == 0) { g_cnt = 0u; g_gen = 0u; }
    if (threadIdx.x < K_MODES)
        g_omega[threadIdx.x] = 0.0625f * (float)threadIdx.x;
}

// mirrored-extension value f[i] for channel base pointer sc
__device__ __forceinline__ float mirror_val(const float* sc, int i) {
    if (i < 4096)  return sc[4095 - i];
    if (i < 12288) return sc[i - 4096];
    return sc[20479 - i];
}

// Real-input FFT-16384 via complex FFT-8192 + untangle. Bins 0..8191 -> g_fpos.
__global__ __launch_bounds__(NTHR, 1) void fwd_fft_kernel(const float* __restrict__ sig) {
    extern __shared__ float2 sh[];   // 8192 float2
    const int c = blockIdx.x;
    const float* sc = sig + c * T_LEN;
    for (int n = threadIdx.x; n < HF; n += NTHR) {
        float a = mirror_val(sc, 2 * n);
        float b = mirror_val(sc, 2 * n + 1);
        sh[__brev((unsigned)n) >> 19] = make_float2(a, b);
    }
    __syncthreads();
    fft_smem(sh, 13, -1.f);
    // F[k] = E + e^{-i*pi*k/8192} * O ; E=(Zk+conj(Zm))/2, O=-i(Zk-conj(Zm))/2
    const int cshift = (c + 8) & 15;
    for (int k = threadIdx.x; k < HF; k += NTHR) {
        float2 Zk = sh[k];
        float2 Zm = sh[(HF - k) & (HF - 1)];
        float ex = 0.5f * (Zk.x + Zm.x), ey = 0.5f * (Zk.y - Zm.y);
        float bx = 0.5f * (Zk.x - Zm.x), by = 0.5f * (Zk.y + Zm.y);
        float ox = by, oy = -bx;
        float sp, cp; sincospif((float)k * (1.0f / (float)HF), &sp, &cp);
        float fx = ex + cp * ox + sp * oy;
        float fy = ey + cp * oy - sp * ox;
        g_fpos[k * C_CH + cshift] = make_float2(fx, fy);
    }
}

// Persistent scan: u[8] in registers, 1 grid barrier per iteration.
__global__ __launch_bounds__(NTHR, 1) void iterate_kernel() {
    const int tid  = threadIdx.x;
    const int e    = blockIdx.x * NTHR + tid;   // e = j*16 + c
    const int j    = e >> 4;
    const int lane = tid & 31;
    const int wid  = tid >> 5;
    const float fh = (float)j * (1.0f / (float)F_LEN);

    __shared__ float s_omega[K_MODES];
    __shared__ float s_wpart[32][16];
    __shared__ float s_red[16];

    if (tid < K_MODES) s_omega[tid] = 0.0625f * (float)tid;
    __syncthreads();

    const float2 fp = g_fpos[e];
    float2 u[K_MODES];
#pragma unroll
    for (int k = 0; k < K_MODES; ++k) u[k] = make_float2(0.f, 0.f);
    float2 sum = make_float2(0.f, 0.f);

    for (int it = 0; it < N_ITERS; ++it) {
        sum.x += u[K_MODES - 1].x - u[0].x;
        sum.y += u[K_MODES - 1].y - u[0].y;
        float2 prev_new = make_float2(0.f, 0.f);
#pragma unroll
        for (int k = 0; k < K_MODES; ++k) {
            if (k > 0) {
                sum.x += prev_new.x - u[k].x;
                sum.y += prev_new.y - u[k].y;
            }
            float d      = fh - s_omega[k];
            float invden = 1.0f / (1.0f + ALPHA_F * d * d);
            float2 un    = make_float2((fp.x - sum.x) * invden, (fp.y - sum.y) * invden);
            u[k] = un;
            prev_new = un;
            float mag = un.x * un.x + un.y * un.y;
            float num = fh * mag;
#pragma unroll
            for (int o = 16; o; o >>= 1) {
                mag += __shfl_down_sync(0xffffffffu, mag, o);
                num += __shfl_down_sync(0xffffffffu, num, o);
            }
            if (lane == 0) {
                s_wpart[wid][k * 2 + 0] = num;
                s_wpart[wid][k * 2 + 1] = mag;
            }
        }
        __syncthreads();
        const int buf = it & 1;
        if (tid < 16) {
            float acc = 0.f;
#pragma unroll
            for (int w = 0; w < 32; ++w) acc += s_wpart[w][tid];
            g_part[buf][blockIdx.x][tid] = acc;
        }
        grid_barrier((unsigned)(it + 1));
        if (tid < 512) {
            const int v = tid >> 5;
            const float* gp = &g_part[buf][0][0];
            float acc = __ldcg(gp + (lane      ) * 16 + v)
                      + __ldcg(gp + (lane +  32) * 16 + v)
                      + __ldcg(gp + (lane +  64) * 16 + v)
                      + __ldcg(gp + (lane +  96) * 16 + v);
#pragma unroll
            for (int o = 16; o; o >>= 1) acc += __shfl_down_sync(0xffffffffu, acc, o);
            if (lane == 0) s_red[v] = acc;
        }
        __syncthreads();
        if (tid < K_MODES) {
            float om = s_red[2 * tid] / s_red[2 * tid + 1];
            s_omega[tid] = om;
            if (blockIdx.x == 0) g_omega[(it + 1) * K_MODES + tid] = om;
        }
        __syncthreads();
    }

    const int c = e & 15;
#pragma unroll
    for (int k = 0; k < K_MODES; ++k)
        g_upos[(j * K_MODES + k) * C_CH + c] = u[k];
}

// Per (k,c_shifted): irfft-16384 via complex ifft-8192 (prep twiddle), slice
// -> u_out; then rfft-8192 via complex fft-4096 + untangle -> u_hat2.
__global__ __launch_bounds__(NTHR, 1) void recon_kernel(float* __restrict__ dout, int mode,
                                                        long long limf) {
    extern __shared__ float2 sh[];
    float2* sh1 = sh;            // 8192 float2
    float2* sh2 = sh + 8192;     // 4096 float2
    float*  rey = (float*)sh;            // overlays sh1 (dead by then)
    float*  imy = ((float*)sh) + 4608;
    const int b   = blockIdx.x;
    const int k   = b >> 4;
    const int c   = b & 15;
    const int tid = threadIdx.x;
    const long long lim2 = limf >> 1;

    // prep: Zc[q] = P + i*Q ; P=H[q]+H[q+M], Q=e^{+i*pi*q/8192}(H[q]-H[q+M])
    // H[0]=Re p0, H[M]=Re p_{M-1}, H[q]=p_q, H[q+M]=conj(p_{M-q})
    for (int q = tid; q < HF; q += NTHR) {
        float2 Hk, HM;
        if (q == 0) {
            float2 p0 = g_upos[(0 * K_MODES + k) * C_CH + c];
            float2 pL = g_upos[((HF - 1) * K_MODES + k) * C_CH + c];
            Hk = make_float2(p0.x, 0.f);
            HM = make_float2(pL.x, 0.f);
        } else {
            Hk = g_upos[(q * K_MODES + k) * C_CH + c];
            float2 pm = g_upos[((HF - q) * K_MODES + k) * C_CH + c];
            HM = make_float2(pm.x, -pm.y);
        }
        float px = Hk.x + HM.x, py = Hk.y + HM.y;
        float dx = Hk.x - HM.x, dy = Hk.y - HM.y;
        float sp, cp; sincospif((float)q * (1.0f / (float)HF), &sp, &cp);
        float qx = cp * dx - sp * dy, qy = cp * dy + sp * dx;
        sh1[__brev((unsigned)q) >> 19] = make_float2(px - qy, py + qx);
    }
    __syncthreads();
    fft_smem(sh1, 13, +1.f);   // z[n]: x[2n]=Re z/N, x[2n+1]=Im z/N

    // u_out (t = 2n, 2n+1 from z[2048+n]) + pack second FFT input zz[n]=z[2048+n]/N
    const float invN = 1.0f / (float)F_LEN;
    const int cs = (c + 8) & 15;
    for (int n = tid; n < 4096; n += NTHR) {
        float2 z = sh1[2048 + n];
        float w0 = z.x * invN, w1 = z.y * invN;
        long long i0 = (long long)(k * T_LEN + 2 * n) * C_CH + cs;
        long long i1 = i0 + C_CH;
        if (mode == MODE_C) {
            float2* o = (float2*)dout;
            if (i0 < lim2) o[i0] = make_float2(w0, 0.f);
            if (i1 < lim2) o[i1] = make_float2(w1, 0.f);
        } else {
            if (i0 < limf) dout[i0] = w0;
            if (i1 < limf) dout[i1] = w1;
        }
        sh2[__brev((unsigned)n) >> 20] = make_float2(w0, w1);
    }
    __syncthreads();
    fft_smem(sh2, 12, -1.f);

    // untangle rfft: Y[q]=E+e^{-i*pi*q/4096}O, q=0..4095; Y[4096]=ReZZ0-ImZZ0
    for (int q = tid; q < 4096; q += NTHR) {
        float2 Zk = sh2[q];
        float2 Zm = sh2[(4096 - q) & 4095];
        float ex = 0.5f * (Zk.x + Zm.x), ey = 0.5f * (Zk.y - Zm.y);
        float bx = 0.5f * (Zk.x - Zm.x), by = 0.5f * (Zk.y + Zm.y);
        float ox = by, oy = -bx;
        float sp, cp; sincospif((float)q * (1.0f / 4096.0f), &sp, &cp);
        rey[q] = ex + cp * ox + sp * oy;
        imy[q] = ey + cp * oy - sp * ox;
        if (q == 0) { rey[4096] = Zk.x - Zk.y; imy[4096] = 0.f; }
    }
    __syncthreads();

    // u_hat2[t][k][c] = conj(Y[t^4096]); real w => Y[8192-b]=conj(Y[b])
    if (mode == MODE_R) {
        const long long base = (long long)T_LEN * K_MODES * C_CH;
        for (int t = tid; t < T_LEN; t += NTHR) {
            int bb = t ^ 4096;
            int rb = (bb <= 4096) ? bb : 8192 - bb;
            long long idx = base + ((long long)t * K_MODES + k) * C_CH + c;
            if (idx < limf) dout[idx] = rey[rb];
        }
    } else {
        const long long base2 = (mode == MODE_M)
            ? (long long)(T_LEN * K_MODES * C_CH / 2)
            : (long long)(T_LEN * K_MODES * C_CH);
        float2* o = (float2*)dout;
        for (int t = tid; t < T_LEN; t += NTHR) {
            int bb = t ^ 4096;
            float re, im;
            if (bb <= 4096) { re = rey[bb];        im = -imy[bb]; }
            else            { re = rey[8192 - bb]; im =  imy[8192 - bb]; }
            long long idx = base2 + ((long long)t * K_MODES + k) * C_CH + c;
            if (idx < lim2) o[idx] = make_float2(re, im);
        }
    }
}

__global__ void omega_out_kernel(float* __restrict__ dout, int mode, long long limf) {
    int i = threadIdx.x;
    if (i >= (N_ITERS + 1) * K_MODES) return;
    if (mode == MODE_R) {
        long long idx = 2097152LL + i;
        if (idx < limf) dout[idx] = g_omega[i];
    } else {
        long long base2 = (mode == MODE_M) ? 1572864LL : 2097152LL;
        long long idx = base2 + i;
        if (idx < (limf >> 1)) ((float2*)dout)[idx] = make_float2(g_omega[i], 0.f);
    }
}

// ---------------- launch ----------------
extern "C" void kernel_launch(void* const* d_in, const int* in_sizes, int n_in,
                              void* d_out, int out_size) {
    const float* sig = (const float*)d_in[0];

    int mode;
    if (out_size == 4194624)      mode = MODE_C;
    else if (out_size == 3146048) mode = MODE_M;
    else                          mode = MODE_R;
    const long long limf = (long long)out_size;

    cudaFuncSetAttribute(fwd_fft_kernel, cudaFuncAttributeMaxDynamicSharedMemorySize, 65536);
    cudaFuncSetAttribute(recon_kernel,   cudaFuncAttributeMaxDynamicSharedMemorySize, 98304);

    init_kernel<<<1, 32>>>();
    fwd_fft_kernel<<<C_CH, NTHR, 65536>>>(sig);
    iterate_kernel<<<NBLK, NTHR>>>();
    recon_kernel<<<NBLK, NTHR, 98304>>>((float*)d_out, mode, limf);
    omega_out_kernel<<<1, 192>>>((float*)d_out, mode, limf);
}